// round 3
// baseline (speedup 1.0000x reference)
#include <cuda_runtime.h>

// LoRALinear: out[T,M] = x[T,K] @ W[M,K]^T + b[M] + alpha * (x @ B)[T,R] @ A[M,R]^T
// Inputs (metadata order): x [T*K], W [M*K], b [M], A [M*R], B [K*R]
// T=8192, M=4096, K=4096, R=8, alpha = 8/R = 1.0

#define MAX_T 8192
#define MAX_RANK 8

// scratch for y = x @ B   [T, R]
static __device__ float g_y[MAX_T * MAX_RANK];

// ---------------------------------------------------------------------------
// Kernel 0: y[t, r] = sum_k x[t,k] * B[k,r]     (one block per token row)
// ---------------------------------------------------------------------------
__global__ __launch_bounds__(256) void xb_kernel(
    const float* __restrict__ x, const float* __restrict__ B,
    float* __restrict__ y, int K, int rank)
{
    const int t = blockIdx.x;
    const float* xrow = x + (size_t)t * K;

    float acc[MAX_RANK];
#pragma unroll
    for (int r = 0; r < MAX_RANK; r++) acc[r] = 0.0f;

    // rank==8 fast path assumed (B rows are 32B-aligned float4 pairs)
    for (int k = threadIdx.x; k < K; k += blockDim.x) {
        float xv = __ldg(xrow + k);
        const float4* Bv = reinterpret_cast<const float4*>(B + (size_t)k * 8);
        float4 b0 = __ldg(Bv + 0);
        float4 b1 = __ldg(Bv + 1);
        acc[0] += xv * b0.x; acc[1] += xv * b0.y;
        acc[2] += xv * b0.z; acc[3] += xv * b0.w;
        acc[4] += xv * b1.x; acc[5] += xv * b1.y;
        acc[6] += xv * b1.z; acc[7] += xv * b1.w;
    }

    // warp reduce
#pragma unroll
    for (int off = 16; off > 0; off >>= 1) {
#pragma unroll
        for (int r = 0; r < MAX_RANK; r++)
            acc[r] += __shfl_down_sync(0xffffffffu, acc[r], off);
    }

    __shared__ float s[8][MAX_RANK];
    const int warp = threadIdx.x >> 5;
    const int lane = threadIdx.x & 31;
    if (lane == 0) {
#pragma unroll
        for (int r = 0; r < MAX_RANK; r++) s[warp][r] = acc[r];
    }
    __syncthreads();
    if (threadIdx.x < (unsigned)rank) {
        float v = 0.0f;
#pragma unroll
        for (int w = 0; w < 8; w++) v += s[w][threadIdx.x];
        y[(size_t)t * rank + threadIdx.x] = v;
    }
}

// ---------------------------------------------------------------------------
// Kernel 1: main GEMM + fused LoRA/bias epilogue
//   BM=128 (T tile), BN=128 (M tile), BK=16, TM=TN=8, 256 threads
// ---------------------------------------------------------------------------
#define BM 128
#define BN 128
#define BK 16
#define TM 8
#define TN 8

__global__ __launch_bounds__(256) void lora_gemm_kernel(
    const float* __restrict__ x,     // [T, K]
    const float* __restrict__ W,     // [M, K]
    const float* __restrict__ bias,  // [M]
    const float* __restrict__ A,     // [M, R]
    const float* __restrict__ y,     // [T, R]
    float* __restrict__ out,         // [T, M]
    int T, int M, int K, float alpha)
{
    __shared__ float xs[BK][BM];   // transposed x tile
    __shared__ float ws[BK][BN];   // transposed W tile

    const int bcol = blockIdx.x;   // M tile
    const int brow = blockIdx.y;   // T tile

    const int tid = threadIdx.x;
    const int threadRow = tid / (BN / TN);   // 0..15
    const int threadCol = tid % (BN / TN);   // 0..15

    const float* xg = x + (size_t)brow * BM * K;
    const float* wg = W + (size_t)bcol * BN * K;

    // loader mapping: 128 rows x 16 cols = 512 float4; 2 per thread
    const int lrow = tid >> 2;            // 0..63
    const int lcol = (tid & 3) * 4;       // 0,4,8,12

    float acc[TM][TN];
#pragma unroll
    for (int i = 0; i < TM; i++)
#pragma unroll
        for (int j = 0; j < TN; j++) acc[i][j] = 0.0f;

    for (int k0 = 0; k0 < K; k0 += BK) {
#pragma unroll
        for (int p = 0; p < 2; p++) {
            int r = lrow + p * 64;
            float4 v = *reinterpret_cast<const float4*>(xg + (size_t)r * K + k0 + lcol);
            xs[lcol + 0][r] = v.x;
            xs[lcol + 1][r] = v.y;
            xs[lcol + 2][r] = v.z;
            xs[lcol + 3][r] = v.w;
        }
#pragma unroll
        for (int p = 0; p < 2; p++) {
            int r = lrow + p * 64;
            float4 v = *reinterpret_cast<const float4*>(wg + (size_t)r * K + k0 + lcol);
            ws[lcol + 0][r] = v.x;
            ws[lcol + 1][r] = v.y;
            ws[lcol + 2][r] = v.z;
            ws[lcol + 3][r] = v.w;
        }
        __syncthreads();

#pragma unroll
        for (int k = 0; k < BK; k++) {
            float4 m0 = *reinterpret_cast<const float4*>(&xs[k][threadRow * TM]);
            float4 m1 = *reinterpret_cast<const float4*>(&xs[k][threadRow * TM + 4]);
            float4 n0 = *reinterpret_cast<const float4*>(&ws[k][threadCol * TN]);
            float4 n1 = *reinterpret_cast<const float4*>(&ws[k][threadCol * TN + 4]);
            float regM[TM] = {m0.x, m0.y, m0.z, m0.w, m1.x, m1.y, m1.z, m1.w};
            float regN[TN] = {n0.x, n0.y, n0.z, n0.w, n1.x, n1.y, n1.z, n1.w};
#pragma unroll
            for (int i = 0; i < TM; i++)
#pragma unroll
                for (int j = 0; j < TN; j++)
                    acc[i][j] += regM[i] * regN[j];
        }
        __syncthreads();
    }

    // ---- epilogue: LoRA correction + bias, vectorized stores ----
    const int rowBase = brow * BM + threadRow * TM;
    const int colBase = bcol * BN + threadCol * TN;

    // add alpha * y[t,:] . A[m,:]
#pragma unroll
    for (int i = 0; i < TM; i++) {
        const float4* yv = reinterpret_cast<const float4*>(y + (size_t)(rowBase + i) * 8);
        float4 y0 = __ldg(yv + 0);
        float4 y1 = __ldg(yv + 1);
#pragma unroll
        for (int j = 0; j < TN; j++) {
            const float4* av = reinterpret_cast<const float4*>(A + (size_t)(colBase + j) * 8);
            float4 a0 = __ldg(av + 0);
            float4 a1 = __ldg(av + 1);
            float l = y0.x * a0.x + y0.y * a0.y + y0.z * a0.z + y0.w * a0.w
                    + y1.x * a1.x + y1.y * a1.y + y1.z * a1.z + y1.w * a1.w;
            acc[i][j] += alpha * l;
        }
    }

    float4 b0 = __ldg(reinterpret_cast<const float4*>(bias + colBase));
    float4 b1 = __ldg(reinterpret_cast<const float4*>(bias + colBase + 4));

#pragma unroll
    for (int i = 0; i < TM; i++) {
        float4 o0, o1;
        o0.x = acc[i][0] + b0.x; o0.y = acc[i][1] + b0.y;
        o0.z = acc[i][2] + b0.z; o0.w = acc[i][3] + b0.w;
        o1.x = acc[i][4] + b1.x; o1.y = acc[i][5] + b1.y;
        o1.z = acc[i][6] + b1.z; o1.w = acc[i][7] + b1.w;
        float* orow = out + (size_t)(rowBase + i) * M + colBase;
        *reinterpret_cast<float4*>(orow)     = o0;
        *reinterpret_cast<float4*>(orow + 4) = o1;
    }
}

// ---------------------------------------------------------------------------
extern "C" void kernel_launch(void* const* d_in, const int* in_sizes, int n_in,
                              void* d_out, int out_size)
{
    const float* x = (const float*)d_in[0];
    const float* W = (const float*)d_in[1];
    const float* b = (const float*)d_in[2];
    const float* A = (const float*)d_in[3];
    const float* B = (const float*)d_in[4];
    float* out = (float*)d_out;

    const int M    = in_sizes[2];              // 4096
    const int rank = in_sizes[3] / M;          // 8
    const int K    = in_sizes[1] / M;          // 4096
    const int T    = in_sizes[0] / K;          // 8192
    const float alpha = 8.0f / (float)rank;    // module: alpha / rank

    float* y;
    cudaGetSymbolAddress((void**)&y, g_y);

    // y = x @ B
    xb_kernel<<<T, 256>>>(x, B, y, K, rank);

    // out = x @ W^T + b + alpha * y @ A^T
    dim3 grid(M / BN, T / BM);
    lora_gemm_kernel<<<grid, 256>>>(x, W, b, A, y, out, T, M, K, alpha);
}

// round 4
// speedup vs baseline: 1.0037x; 1.0037x over previous
#include <cuda_runtime.h>

// LoRALinear: out[T,M] = x[T,K] @ W[M,K]^T + b[M] + alpha * (x @ B)[T,R] @ A[M,R]^T
// Inputs (metadata order): x [T*K], W [M*K], b [M], A [M*R], B [K*R]
// T=8192, M=4096, K=4096, R=8, alpha = 8/R = 1.0

#define MAX_T 8192
#define MAX_RANK 8

// scratch for y = x @ B   [T, R]
static __device__ float g_y[MAX_T * MAX_RANK];

// ---------------------------------------------------------------------------
// Kernel 0: y[t, r] = sum_k x[t,k] * B[k,r]     (one block per token row)
// ---------------------------------------------------------------------------
__global__ __launch_bounds__(256) void xb_kernel(
    const float* __restrict__ x, const float* __restrict__ B,
    float* __restrict__ y, int K, int rank)
{
    const int t = blockIdx.x;
    const float* xrow = x + (size_t)t * K;

    float acc[MAX_RANK];
#pragma unroll
    for (int r = 0; r < MAX_RANK; r++) acc[r] = 0.0f;

    // rank==8 fast path assumed (B rows are 32B-aligned float4 pairs)
    for (int k = threadIdx.x; k < K; k += blockDim.x) {
        float xv = __ldg(xrow + k);
        const float4* Bv = reinterpret_cast<const float4*>(B + (size_t)k * 8);
        float4 b0 = __ldg(Bv + 0);
        float4 b1 = __ldg(Bv + 1);
        acc[0] += xv * b0.x; acc[1] += xv * b0.y;
        acc[2] += xv * b0.z; acc[3] += xv * b0.w;
        acc[4] += xv * b1.x; acc[5] += xv * b1.y;
        acc[6] += xv * b1.z; acc[7] += xv * b1.w;
    }

    // warp reduce
#pragma unroll
    for (int off = 16; off > 0; off >>= 1) {
#pragma unroll
        for (int r = 0; r < MAX_RANK; r++)
            acc[r] += __shfl_down_sync(0xffffffffu, acc[r], off);
    }

    __shared__ float s[8][MAX_RANK];
    const int warp = threadIdx.x >> 5;
    const int lane = threadIdx.x & 31;
    if (lane == 0) {
#pragma unroll
        for (int r = 0; r < MAX_RANK; r++) s[warp][r] = acc[r];
    }
    __syncthreads();
    if (threadIdx.x < (unsigned)rank) {
        float v = 0.0f;
#pragma unroll
        for (int w = 0; w < 8; w++) v += s[w][threadIdx.x];
        y[(size_t)t * rank + threadIdx.x] = v;
    }
}

// ---------------------------------------------------------------------------
// Kernel 1: main GEMM + fused LoRA/bias epilogue
//   BM=128 (T tile), BN=128 (M tile), BK=16, TM=TN=8, 256 threads
// ---------------------------------------------------------------------------
#define BM 128
#define BN 128
#define BK 16
#define TM 8
#define TN 8

__global__ __launch_bounds__(256) void lora_gemm_kernel(
    const float* __restrict__ x,     // [T, K]
    const float* __restrict__ W,     // [M, K]
    const float* __restrict__ bias,  // [M]
    const float* __restrict__ A,     // [M, R]
    const float* __restrict__ y,     // [T, R]
    float* __restrict__ out,         // [T, M]
    int T, int M, int K, float alpha)
{
    __shared__ float xs[BK][BM];   // transposed x tile
    __shared__ float ws[BK][BN];   // transposed W tile

    const int bcol = blockIdx.x;   // M tile
    const int brow = blockIdx.y;   // T tile

    const int tid = threadIdx.x;
    const int threadRow = tid / (BN / TN);   // 0..15
    const int threadCol = tid % (BN / TN);   // 0..15

    const float* xg = x + (size_t)brow * BM * K;
    const float* wg = W + (size_t)bcol * BN * K;

    // loader mapping: 128 rows x 16 cols = 512 float4; 2 per thread
    const int lrow = tid >> 2;            // 0..63
    const int lcol = (tid & 3) * 4;       // 0,4,8,12

    float acc[TM][TN];
#pragma unroll
    for (int i = 0; i < TM; i++)
#pragma unroll
        for (int j = 0; j < TN; j++) acc[i][j] = 0.0f;

    for (int k0 = 0; k0 < K; k0 += BK) {
#pragma unroll
        for (int p = 0; p < 2; p++) {
            int r = lrow + p * 64;
            float4 v = *reinterpret_cast<const float4*>(xg + (size_t)r * K + k0 + lcol);
            xs[lcol + 0][r] = v.x;
            xs[lcol + 1][r] = v.y;
            xs[lcol + 2][r] = v.z;
            xs[lcol + 3][r] = v.w;
        }
#pragma unroll
        for (int p = 0; p < 2; p++) {
            int r = lrow + p * 64;
            float4 v = *reinterpret_cast<const float4*>(wg + (size_t)r * K + k0 + lcol);
            ws[lcol + 0][r] = v.x;
            ws[lcol + 1][r] = v.y;
            ws[lcol + 2][r] = v.z;
            ws[lcol + 3][r] = v.w;
        }
        __syncthreads();

#pragma unroll
        for (int k = 0; k < BK; k++) {
            float4 m0 = *reinterpret_cast<const float4*>(&xs[k][threadRow * TM]);
            float4 m1 = *reinterpret_cast<const float4*>(&xs[k][threadRow * TM + 4]);
            float4 n0 = *reinterpret_cast<const float4*>(&ws[k][threadCol * TN]);
            float4 n1 = *reinterpret_cast<const float4*>(&ws[k][threadCol * TN + 4]);
            float regM[TM] = {m0.x, m0.y, m0.z, m0.w, m1.x, m1.y, m1.z, m1.w};
            float regN[TN] = {n0.x, n0.y, n0.z, n0.w, n1.x, n1.y, n1.z, n1.w};
#pragma unroll
            for (int i = 0; i < TM; i++)
#pragma unroll
                for (int j = 0; j < TN; j++)
                    acc[i][j] += regM[i] * regN[j];
        }
        __syncthreads();
    }

    // ---- epilogue: LoRA correction + bias, vectorized stores ----
    const int rowBase = brow * BM + threadRow * TM;
    const int colBase = bcol * BN + threadCol * TN;

    // add alpha * y[t,:] . A[m,:]
#pragma unroll
    for (int i = 0; i < TM; i++) {
        const float4* yv = reinterpret_cast<const float4*>(y + (size_t)(rowBase + i) * 8);
        float4 y0 = __ldg(yv + 0);
        float4 y1 = __ldg(yv + 1);
#pragma unroll
        for (int j = 0; j < TN; j++) {
            const float4* av = reinterpret_cast<const float4*>(A + (size_t)(colBase + j) * 8);
            float4 a0 = __ldg(av + 0);
            float4 a1 = __ldg(av + 1);
            float l = y0.x * a0.x + y0.y * a0.y + y0.z * a0.z + y0.w * a0.w
                    + y1.x * a1.x + y1.y * a1.y + y1.z * a1.z + y1.w * a1.w;
            acc[i][j] += alpha * l;
        }
    }

    float4 b0 = __ldg(reinterpret_cast<const float4*>(bias + colBase));
    float4 b1 = __ldg(reinterpret_cast<const float4*>(bias + colBase + 4));

#pragma unroll
    for (int i = 0; i < TM; i++) {
        float4 o0, o1;
        o0.x = acc[i][0] + b0.x; o0.y = acc[i][1] + b0.y;
        o0.z = acc[i][2] + b0.z; o0.w = acc[i][3] + b0.w;
        o1.x = acc[i][4] + b1.x; o1.y = acc[i][5] + b1.y;
        o1.z = acc[i][6] + b1.z; o1.w = acc[i][7] + b1.w;
        float* orow = out + (size_t)(rowBase + i) * M + colBase;
        *reinterpret_cast<float4*>(orow)     = o0;
        *reinterpret_cast<float4*>(orow + 4) = o1;
    }
}

// ---------------------------------------------------------------------------
extern "C" void kernel_launch(void* const* d_in, const int* in_sizes, int n_in,
                              void* d_out, int out_size)
{
    const float* x = (const float*)d_in[0];
    const float* W = (const float*)d_in[1];
    const float* b = (const float*)d_in[2];
    const float* A = (const float*)d_in[3];
    const float* B = (const float*)d_in[4];
    float* out = (float*)d_out;

    const int M    = in_sizes[2];              // 4096
    const int rank = in_sizes[3] / M;          // 8
    const int K    = in_sizes[1] / M;          // 4096
    const int T    = in_sizes[0] / K;          // 8192
    const float alpha = 8.0f / (float)rank;    // module: alpha / rank

    float* y;
    cudaGetSymbolAddress((void**)&y, g_y);

    // y = x @ B
    xb_kernel<<<T, 256>>>(x, B, y, K, rank);

    // out = x @ W^T + b + alpha * y @ A^T
    dim3 grid(M / BN, T / BM);
    lora_gemm_kernel<<<grid, 256>>>(x, W, b, A, y, out, T, M, K, alpha);
}